// round 4
// baseline (speedup 1.0000x reference)
#include <cuda_runtime.h>

#define TB      64      // batch rows per CTA
#define THREADS 512
#define HID     256
#define ND      64      // num dense features

#define DST     68      // dense smem row stride (floats, even)
#define HST     68      // hidden smem row stride (floats, even)

// --- packed f32x2 helpers (sm_103a FFMA2 path; ptxas never auto-fuses) ---
__device__ __forceinline__ unsigned long long pack2(float lo, float hi) {
    unsigned long long r;
    asm("mov.b64 %0, {%1, %2};" : "=l"(r) : "f"(lo), "f"(hi));
    return r;
}
__device__ __forceinline__ void unpack2(unsigned long long v, float& lo, float& hi) {
    asm("mov.b64 {%0, %1}, %2;" : "=f"(lo), "=f"(hi) : "l"(v));
}
__device__ __forceinline__ unsigned long long fma2(unsigned long long a, unsigned long long b,
                                                   unsigned long long c) {
    unsigned long long d;
    asm("fma.rn.f32x2 %0, %1, %2, %3;" : "=l"(d) : "l"(a), "l"(b), "l"(c));
    return d;
}
__device__ __forceinline__ unsigned long long add2(unsigned long long a, unsigned long long b) {
    unsigned long long d;
    asm("add.rn.f32x2 %0, %1, %2;" : "=l"(d) : "l"(a), "l"(b));
    return d;
}

__global__ __launch_bounds__(THREADS, 2)
void ddm_fused_kernel(const float* __restrict__ dense,
                      const int* __restrict__ sparse_i32,   // raw words; dtype autodetected
                      const float* __restrict__ W1,
                      const float* __restrict__ b1,
                      const float* __restrict__ W2,
                      const float* __restrict__ b2,
                      float* __restrict__ out) {
    // cumulative one-hot block offsets: 64 + prefix(CARDS)
    const int OFFS[8] = {64, 1064, 1564, 1764, 1864, 1914, 1964, 1984};

    extern __shared__ float smem[];
    float* d_sh    = smem;                         // [64][DST]   dense transposed
    int*   rows_sh = (int*)(smem + 64 * DST);      // [TB][8]     gather row ids
    float* h_sh    = smem + 64 * DST + TB * 8;     // [256][HST]  hidden transposed

    const int tid = threadIdx.x;
    const int b0  = blockIdx.x * TB;

    // ---- dtype autodetect: values in [0,10). int64(LE) -> every odd i32 word
    // of the first 64 elements is 0; int32 -> P(all zero) ~ 1e-64.
    int odd_or = 0;
#pragma unroll
    for (int i = 0; i < 64; i++) odd_or |= __ldg(&sparse_i32[2 * i + 1]);
    const int is64 = (odd_or == 0);

    // ---- stage dense tile transposed: d_sh[k][b] = dense[b0+b][k] ----
    for (int i = tid; i < TB * ND; i += THREADS) {
        int b = i >> 6, k = i & 63;
        d_sh[k * DST + b] = dense[(size_t)b0 * ND + i];
    }
    // ---- stage gather rows (clamped as a safety net) ----
    for (int i = tid; i < TB * 8; i += THREADS) {
        int f = i & 7;
        size_t gidx = (size_t)b0 * 8 + i;
        int v = is64 ? sparse_i32[2 * gidx] : sparse_i32[gidx];
        int r = OFFS[f] + v;
        rows_sh[i] = min(max(r, 0), 1993);
    }
    __syncthreads();

    // thread tiling: 4 consecutive cols (c0..c0+3) x 8 rows
    const int tx = tid & 63;
    const int ty = tid >> 6;          // 0..7
    const int c0 = tx * 4;
    const int r0 = ty * 8;

    unsigned long long acc[4][4];     // [col][row-pair]  (32 regs)

    // ================= Phase 1: h = relu(dense@W1[0:64] + gathers + b1) =================
    {
        float4 b = *(const float4*)&b1[c0];
        acc[0][0] = pack2(b.x, b.x); acc[1][0] = pack2(b.y, b.y);
        acc[2][0] = pack2(b.z, b.z); acc[3][0] = pack2(b.w, b.w);
#pragma unroll
        for (int p = 1; p < 4; p++) {
            acc[0][p] = acc[0][0]; acc[1][p] = acc[1][0];
            acc[2][p] = acc[2][0]; acc[3][p] = acc[3][0];
        }
    }

#pragma unroll 4
    for (int k = 0; k < ND; k++) {
        float4 w = *(const float4*)&W1[(size_t)k * HID + c0];   // LDG.128
        unsigned long long w0 = pack2(w.x, w.x), w1 = pack2(w.y, w.y);
        unsigned long long w2 = pack2(w.z, w.z), w3 = pack2(w.w, w.w);
        const unsigned long long* dp =
            (const unsigned long long*)(d_sh + k * DST + r0);   // broadcast b64 loads
#pragma unroll
        for (int p = 0; p < 4; p++) {
            unsigned long long dv = dp[p];
            acc[0][p] = fma2(dv, w0, acc[0][p]);
            acc[1][p] = fma2(dv, w1, acc[1][p]);
            acc[2][p] = fma2(dv, w2, acc[2][p]);
            acc[3][p] = fma2(dv, w3, acc[3][p]);
        }
    }

    // gathers: + sum_f W1[row_f(b)][c]  (all lanes share row -> coalesced LDG.128)
    {
        const int* rp = rows_sh + r0 * 8;
#pragma unroll
        for (int p = 0; p < 4; p++) {
#pragma unroll
            for (int f = 0; f < 8; f++) {
                int ra = rp[(2 * p) * 8 + f];
                int rb = rp[(2 * p + 1) * 8 + f];
                float4 ga = *(const float4*)&W1[(size_t)ra * HID + c0];
                float4 gb = *(const float4*)&W1[(size_t)rb * HID + c0];
                acc[0][p] = add2(pack2(ga.x, gb.x), acc[0][p]);
                acc[1][p] = add2(pack2(ga.y, gb.y), acc[1][p]);
                acc[2][p] = add2(pack2(ga.z, gb.z), acc[2][p]);
                acc[3][p] = add2(pack2(ga.w, gb.w), acc[3][p]);
            }
        }
    }

    // relu + store h transposed: h_sh[col][row]
#pragma unroll
    for (int p = 0; p < 4; p++) {
#pragma unroll
        for (int c = 0; c < 4; c++) {
            float x0, x1;
            unpack2(acc[c][p], x0, x1);
            x0 = fmaxf(x0, 0.f); x1 = fmaxf(x1, 0.f);
            *(float2*)&h_sh[(c0 + c) * HST + r0 + 2 * p] = make_float2(x0, x1);
        }
    }
    __syncthreads();

    // ================= Phase 2: out = h @ W2 + b2 =================
    {
        float4 b = *(const float4*)&b2[c0];
        acc[0][0] = pack2(b.x, b.x); acc[1][0] = pack2(b.y, b.y);
        acc[2][0] = pack2(b.z, b.z); acc[3][0] = pack2(b.w, b.w);
#pragma unroll
        for (int p = 1; p < 4; p++) {
            acc[0][p] = acc[0][0]; acc[1][p] = acc[1][0];
            acc[2][p] = acc[2][0]; acc[3][p] = acc[3][0];
        }
    }

#pragma unroll 4
    for (int jj = 0; jj < HID; jj++) {
        float4 w = *(const float4*)&W2[(size_t)jj * HID + c0];  // LDG.128
        unsigned long long w0 = pack2(w.x, w.x), w1 = pack2(w.y, w.y);
        unsigned long long w2 = pack2(w.z, w.z), w3 = pack2(w.w, w.w);
        const unsigned long long* hp =
            (const unsigned long long*)(h_sh + jj * HST + r0);  // broadcast b64 loads
#pragma unroll
        for (int p = 0; p < 4; p++) {
            unsigned long long hv = hp[p];
            acc[0][p] = fma2(hv, w0, acc[0][p]);
            acc[1][p] = fma2(hv, w1, acc[1][p]);
            acc[2][p] = fma2(hv, w2, acc[2][p]);
            acc[3][p] = fma2(hv, w3, acc[3][p]);
        }
    }

    // write out: two float4 stores per row-pair (coalesced across tx)
#pragma unroll
    for (int p = 0; p < 4; p++) {
        float a0, a1, bb0, bb1, cc0, cc1, dd0, dd1;
        unpack2(acc[0][p], a0, a1);
        unpack2(acc[1][p], bb0, bb1);
        unpack2(acc[2][p], cc0, cc1);
        unpack2(acc[3][p], dd0, dd1);
        size_t rowa = (size_t)(b0 + r0 + 2 * p) * HID;
        size_t rowb = rowa + HID;
        *(float4*)&out[rowa + c0] = make_float4(a0, bb0, cc0, dd0);
        *(float4*)&out[rowb + c0] = make_float4(a1, bb1, cc1, dd1);
    }
}

extern "C" void kernel_launch(void* const* d_in, const int* in_sizes, int n_in,
                              void* d_out, int out_size) {
    const float* dense  = (const float*)d_in[0];
    const int*   sparse = (const int*)d_in[1];
    const float* W1     = (const float*)d_in[2];
    const float* b1     = (const float*)d_in[3];
    const float* W2     = (const float*)d_in[4];
    const float* b2     = (const float*)d_in[5];
    float*       out    = (float*)d_out;

    int B = in_sizes[0] / ND;                 // 16384
    int grid = B / TB;                        // 256 CTAs

    int smem_bytes = (64 * DST) * 4 + TB * 8 * 4 + (HID * HST) * 4;  // 89088 B
    cudaFuncSetAttribute(ddm_fused_kernel,
                         cudaFuncAttributeMaxDynamicSharedMemorySize, smem_bytes);

    ddm_fused_kernel<<<grid, THREADS, smem_bytes>>>(dense, sparse, W1, b1, W2, b2, out);
}